// round 12
// baseline (speedup 1.0000x reference)
#include <cuda_runtime.h>
#include <cstdint>

// N=65536, D=512, C=1000.
// Bulk-async (UBLKCP) producer/consumer pipeline. One 16KB cp.async.bulk per
// 8-row x-chunk (the documented path that reaches the ~6300 B/cyc LTS cap),
// mbarrier expect_tx completion, 6 stages x 16KB = 96KB smem, 304 blocks
// (2/SM). Thread 0 produces with lookahead 6; all 8 warps consume
// warp-per-row; w/t prefetched before the full-wait so gather latency hides
// in the spin. No __syncthreads in the main loop. Fused deterministic finish.

#define N_ROWS   65536
#define D_DIM    512
#define BLOCKS   304
#define THREADS  256
#define WARPS    8
#define CHUNK_ROWS   8
#define CHUNK_FLOATS (CHUNK_ROWS * D_DIM)     // 4096
#define CHUNK_BYTES  (CHUNK_FLOATS * 4)       // 16384
#define NCHUNKS  (N_ROWS / CHUNK_ROWS)        // 8192
#define STAGES   6
#define SMEM_BYTES (STAGES * CHUNK_BYTES)     // 98304

__device__ float g_partial[BLOCKS];
__device__ int   g_count;   // zero-init; last block resets each call

__device__ __forceinline__ uint32_t s2u(const void* p) {
    return (uint32_t)__cvta_generic_to_shared(p);
}
__device__ __forceinline__ void mbar_init(uint32_t a, uint32_t n) {
    asm volatile("mbarrier.init.shared.b64 [%0], %1;" :: "r"(a), "r"(n) : "memory");
}
__device__ __forceinline__ void mbar_arrive(uint32_t a) {
    asm volatile("mbarrier.arrive.shared.b64 _, [%0];" :: "r"(a) : "memory");
}
__device__ __forceinline__ void mbar_expect_tx(uint32_t a, uint32_t bytes) {
    asm volatile("mbarrier.arrive.expect_tx.shared.b64 _, [%0], %1;"
                 :: "r"(a), "r"(bytes) : "memory");
}
__device__ __forceinline__ void mbar_wait(uint32_t a, uint32_t phase) {
    uint32_t done;
    asm volatile(
        "{\n\t.reg .pred p;\n\t"
        "mbarrier.try_wait.parity.acquire.cta.shared::cta.b64 p, [%1], %2;\n\t"
        "selp.b32 %0, 1, 0, p;\n\t}"
        : "=r"(done) : "r"(a), "r"(phase) : "memory");
    while (!done) {
        asm volatile(
            "{\n\t.reg .pred p;\n\t"
            "mbarrier.try_wait.parity.acquire.cta.shared::cta.b64 p, [%1], %2, 0x989680;\n\t"
            "selp.b32 %0, 1, 0, p;\n\t}"
            : "=r"(done) : "r"(a), "r"(phase) : "memory");
    }
}
__device__ __forceinline__ void bulk_g2s(uint32_t dst, const float* src,
                                         uint32_t bytes, uint32_t mbar) {
    asm volatile(
        "cp.async.bulk.shared::cta.global.mbarrier::complete_tx::bytes [%0], [%1], %2, [%3];"
        :: "r"(dst), "l"(src), "r"(bytes), "r"(mbar) : "memory");
}

__global__ __launch_bounds__(THREADS) void center_loss_bulk(
    const float* __restrict__ x,
    const float* __restrict__ w,
    const int*   __restrict__ t,
    float* __restrict__ out)
{
    extern __shared__ float smem[];
    __shared__ uint64_t mbar[2 * STAGES];   // [0..5]=full, [6..11]=empty

    const int tid  = threadIdx.x;
    const int wid  = tid >> 5;
    const int lane = tid & 31;
    const int bid  = blockIdx.x;

    const uint32_t smem_u = s2u(smem);
    const uint32_t full0  = s2u(&mbar[0]);
    const uint32_t empty0 = s2u(&mbar[STAGES]);

    if (tid == 0) {
        #pragma unroll
        for (int s = 0; s < STAGES; s++) {
            mbar_init(full0  + 8u * s, 1);       // producer's expect_tx arrive
            mbar_init(empty0 + 8u * s, WARPS);   // one arrive per consumer warp
        }
    }
    __syncthreads();

    // chunks for this block: c = bid + i*BLOCKS, i in [0, nch)
    const int nch = (NCHUNKS - bid + BLOCKS - 1) / BLOCKS;

    int pslot = 0, pphase = 1;   // producer cursor (phase 1: first waits pass)
    if (tid == 0) {
        const int np = nch < STAGES ? nch : STAGES;
        for (int i = 0; i < np; i++) {
            mbar_wait(empty0 + 8u * pslot, (uint32_t)pphase);
            mbar_expect_tx(full0 + 8u * pslot, CHUNK_BYTES);
            const size_t c = (size_t)bid + (size_t)i * BLOCKS;
            bulk_g2s(smem_u + (uint32_t)pslot * CHUNK_BYTES,
                     x + c * CHUNK_FLOATS, CHUNK_BYTES, full0 + 8u * pslot);
            if (++pslot == STAGES) { pslot = 0; pphase ^= 1; }
        }
    }

    float runsum = 0.0f;
    int cslot = 0, cphase = 0;   // consumer cursor

    for (int i = 0; i < nch; i++) {
        const int c   = bid + i * BLOCKS;
        const int row = c * CHUNK_ROWS + wid;

        // prefetch t + w BEFORE waiting: latency hides inside the spin
        const int cls = __ldg(&t[row]);
        const float4* wr = reinterpret_cast<const float4*>(w + (size_t)cls * D_DIM);
        float4 b0 = __ldg(&wr[lane +  0]);
        float4 b1 = __ldg(&wr[lane + 32]);
        float4 b2 = __ldg(&wr[lane + 64]);
        float4 b3 = __ldg(&wr[lane + 96]);

        mbar_wait(full0 + 8u * cslot, (uint32_t)cphase);

        const float4* xs = reinterpret_cast<const float4*>(
            smem + (size_t)cslot * CHUNK_FLOATS + wid * D_DIM);
        float4 a0 = xs[lane +  0];
        float4 a1 = xs[lane + 32];
        float4 a2 = xs[lane + 64];
        float4 a3 = xs[lane + 96];

        float acc = 0.0f, d;
        d = a0.x - b0.x; acc = fmaf(d, d, acc);
        d = a0.y - b0.y; acc = fmaf(d, d, acc);
        d = a0.z - b0.z; acc = fmaf(d, d, acc);
        d = a0.w - b0.w; acc = fmaf(d, d, acc);
        d = a1.x - b1.x; acc = fmaf(d, d, acc);
        d = a1.y - b1.y; acc = fmaf(d, d, acc);
        d = a1.z - b1.z; acc = fmaf(d, d, acc);
        d = a1.w - b1.w; acc = fmaf(d, d, acc);
        d = a2.x - b2.x; acc = fmaf(d, d, acc);
        d = a2.y - b2.y; acc = fmaf(d, d, acc);
        d = a2.z - b2.z; acc = fmaf(d, d, acc);
        d = a2.w - b2.w; acc = fmaf(d, d, acc);
        d = a3.x - b3.x; acc = fmaf(d, d, acc);
        d = a3.y - b3.y; acc = fmaf(d, d, acc);
        d = a3.z - b3.z; acc = fmaf(d, d, acc);
        d = a3.w - b3.w; acc = fmaf(d, d, acc);

        #pragma unroll
        for (int o = 16; o > 0; o >>= 1)
            acc += __shfl_xor_sync(0xFFFFFFFFu, acc, o);
        runsum += sqrtf(acc + 1e-6f);

        if (lane == 0) mbar_arrive(empty0 + 8u * cslot);
        if (++cslot == STAGES) { cslot = 0; cphase ^= 1; }

        // producer: refill for chunk i+STAGES (same slot just consumed)
        if (tid == 0 && i + STAGES < nch) {
            mbar_wait(empty0 + 8u * pslot, (uint32_t)pphase);
            mbar_expect_tx(full0 + 8u * pslot, CHUNK_BYTES);
            const size_t c2 = (size_t)bid + (size_t)(i + STAGES) * BLOCKS;
            bulk_g2s(smem_u + (uint32_t)pslot * CHUNK_BYTES,
                     x + c2 * CHUNK_FLOATS, CHUNK_BYTES, full0 + 8u * pslot);
            if (++pslot == STAGES) { pslot = 0; pphase ^= 1; }
        }
    }

    // block reduction of per-warp sums (runsum replicated across lanes)
    __shared__ float sred[WARPS];
    if (lane == 0) sred[wid] = runsum;
    __syncthreads();

    __shared__ bool is_last;
    if (tid == 0) {
        float v = 0.0f;
        #pragma unroll
        for (int i = 0; i < WARPS; i++) v += sred[i];
        g_partial[bid] = v;
        __threadfence();
        int old = atomicAdd(&g_count, 1);
        is_last = (old == BLOCKS - 1);
    }
    __syncthreads();

    if (is_last) {
        float v = (tid < BLOCKS) ? g_partial[tid] : 0.0f;
        if (tid + THREADS < BLOCKS) v += g_partial[tid + THREADS];
        #pragma unroll
        for (int o = 16; o > 0; o >>= 1)
            v += __shfl_xor_sync(0xFFFFFFFFu, v, o);
        __shared__ float fs[WARPS];
        if (lane == 0) fs[wid] = v;
        __syncthreads();
        if (tid < 32) {
            float u = (lane < WARPS) ? fs[lane] : 0.0f;
            #pragma unroll
            for (int o = 16; o > 0; o >>= 1)
                u += __shfl_xor_sync(0xFFFFFFFFu, u, o);
            if (tid == 0) {
                out[0] = u * (1.0f / (float)N_ROWS);
                g_count = 0;   // reset for next graph replay
            }
        }
    }
}

extern "C" void kernel_launch(void* const* d_in, const int* in_sizes, int n_in,
                              void* d_out, int out_size)
{
    const float* x = (const float*)d_in[0];   // [N, D] fp32
    const float* w = (const float*)d_in[1];   // [C, D] fp32
    const int*   t = (const int*)d_in[2];     // [N] int32
    float* out = (float*)d_out;

    cudaFuncSetAttribute(center_loss_bulk,
                         cudaFuncAttributeMaxDynamicSharedMemorySize, SMEM_BYTES);
    center_loss_bulk<<<BLOCKS, THREADS, SMEM_BYTES>>>(x, w, t, out);
}

// round 13
// speedup vs baseline: 1.1506x; 1.1506x over previous
#include <cuda_runtime.h>

// N=65536, D=512, C=1000.
// R1's main loop verbatim (fastest measured main: 27.8us) — warp-per-row,
// plain __ldg float4 for both x and w, 8192 blocks x 256 threads — plus the
// fused deterministic last-block-done finish (replaces R1's 5.5us second
// kernel). All fancier load machinery (cp.async, bulk/TMA, evict hints,
// class binning) measured SLOWER; the ~4.5TB/s operating point is the
// platform ceiling for this stream+gather mix.

#define N_ROWS   65536
#define D_DIM    512
#define THREADS  256
#define WARPS_PER_BLOCK 8
#define NBLOCKS  (N_ROWS / WARPS_PER_BLOCK)   // 8192

__device__ float g_partial[NBLOCKS];
__device__ int   g_count;   // zero-init; last block resets each call

__global__ __launch_bounds__(THREADS) void center_loss_r1f(
    const float* __restrict__ x,
    const float* __restrict__ w,
    const int*   __restrict__ t,
    float* __restrict__ out)
{
    const int tid  = threadIdx.x;
    const int wid  = tid >> 5;
    const int lane = tid & 31;
    const int row  = blockIdx.x * WARPS_PER_BLOCK + wid;

    const float4* xr = reinterpret_cast<const float4*>(x + (size_t)row * D_DIM);
    const int cls = t[row];
    const float4* wr = reinterpret_cast<const float4*>(w + (size_t)cls * D_DIM);

    float acc = 0.0f;
    // 512 floats / 32 lanes = 4 float4 per lane (R1 pattern, untouched)
    #pragma unroll
    for (int i = 0; i < 4; i++) {
        float4 a = xr[lane + i * 32];
        float4 b = __ldg(&wr[lane + i * 32]);
        float d0 = a.x - b.x;
        float d1 = a.y - b.y;
        float d2 = a.z - b.z;
        float d3 = a.w - b.w;
        acc = fmaf(d0, d0, acc);
        acc = fmaf(d1, d1, acc);
        acc = fmaf(d2, d2, acc);
        acc = fmaf(d3, d3, acc);
    }

    // warp reduce
    #pragma unroll
    for (int o = 16; o > 0; o >>= 1)
        acc += __shfl_xor_sync(0xFFFFFFFFu, acc, o);

    __shared__ float s[WARPS_PER_BLOCK];
    if (lane == 0)
        s[wid] = sqrtf(acc + 1e-6f);
    __syncthreads();

    __shared__ bool is_last;
    if (tid == 0) {
        float v = 0.0f;
        #pragma unroll
        for (int i = 0; i < WARPS_PER_BLOCK; i++) v += s[i];
        g_partial[blockIdx.x] = v;
        __threadfence();
        int old = atomicAdd(&g_count, 1);
        is_last = (old == NBLOCKS - 1);
    }
    __syncthreads();

    if (is_last) {
        // deterministic reduce over 8192 partials with 256 threads (32 each)
        float v = 0.0f;
        #pragma unroll
        for (int i = 0; i < NBLOCKS / THREADS; i++)
            v += g_partial[tid + i * THREADS];
        #pragma unroll
        for (int o = 16; o > 0; o >>= 1)
            v += __shfl_xor_sync(0xFFFFFFFFu, v, o);
        __shared__ float fs[WARPS_PER_BLOCK];
        if (lane == 0) fs[wid] = v;
        __syncthreads();
        if (tid < 32) {
            float u = (lane < WARPS_PER_BLOCK) ? fs[lane] : 0.0f;
            #pragma unroll
            for (int o = 16; o > 0; o >>= 1)
                u += __shfl_xor_sync(0xFFFFFFFFu, u, o);
            if (tid == 0) {
                out[0] = u * (1.0f / (float)N_ROWS);
                g_count = 0;   // reset for next graph replay
            }
        }
    }
}

extern "C" void kernel_launch(void* const* d_in, const int* in_sizes, int n_in,
                              void* d_out, int out_size)
{
    const float* x = (const float*)d_in[0];   // [N, D] fp32
    const float* w = (const float*)d_in[1];   // [C, D] fp32
    const int*   t = (const int*)d_in[2];     // [N] int32
    float* out = (float*)d_out;

    center_loss_r1f<<<NBLOCKS, THREADS>>>(x, w, t, out);
}